// round 17
// baseline (speedup 1.0000x reference)
#include <cuda_runtime.h>
#include <cuda_fp16.h>

#define NV   6
#define C    16
#define IMH  480
#define IMW  640
#define DVOL 96
#define PVOX (DVOL*DVOL*DVOL)
#define HW   (IMH*IMW)

// Split channel-packed fp16 scratch (SoA): lo = channels 0-7, hi = channels 8-15.
__device__ uint4 g_feat_lo[(size_t)NV * HW];
__device__ uint4 g_feat_hi[(size_t)NV * HW];

// ---------------------------------------------------------------------------
// Per-view projection build: P = K(3x4) @ w2c(4x4), w2c = [R^T, -R^T t].
// ---------------------------------------------------------------------------
__device__ __forceinline__ void build_view_matrix(const float* __restrict__ intrs,
                                                  const float* __restrict__ c2ws,
                                                  int v, float* __restrict__ dstM) {
    const float* cm = c2ws + v * 16;
    float R[9], t[3];
#pragma unroll
    for (int r = 0; r < 3; r++) {
#pragma unroll
        for (int c = 0; c < 3; c++) R[r * 3 + c] = cm[r * 4 + c];
        t[r] = cm[r * 4 + 3];
    }
    float w2c[12];
#pragma unroll
    for (int r = 0; r < 3; r++) {
#pragma unroll
        for (int c = 0; c < 3; c++) w2c[r * 4 + c] = R[c * 3 + r];  // R^T
        w2c[r * 4 + 3] = -(R[0 * 3 + r] * t[0] + R[1 * 3 + r] * t[1] + R[2 * 3 + r] * t[2]);
    }
    const float* K = intrs + v * 12;
#pragma unroll
    for (int r = 0; r < 3; r++) {
#pragma unroll
        for (int c = 0; c < 4; c++) {
            float s = 0.f;
#pragma unroll
            for (int k = 0; k < 3; k++) s += K[r * 4 + k] * w2c[k * 4 + c];
            if (c == 3) s += K[r * 4 + 3];
            dstM[r * 4 + c] = s;
        }
    }
}

// ---------------------------------------------------------------------------
// Transpose + fp16 pack (1 pixel/thread, known-good): planar fp32 -> split SoA half.
// ---------------------------------------------------------------------------
__global__ __launch_bounds__(256) void transpose_kernel(const float* __restrict__ feat) {
    int p = blockIdx.x * blockDim.x + threadIdx.x;  // pixel id in [0, NV*HW)
    if (p >= NV * HW) return;
    int v = p / HW;
    int pix = p - v * HW;
    const float* base = feat + (size_t)v * C * HW + pix;

    float f[C];
#pragma unroll
    for (int ch = 0; ch < C; ch++) f[ch] = __ldcs(base + (size_t)ch * HW);

    __half2 h[8];
#pragma unroll
    for (int r = 0; r < 8; r++) h[r] = __floats2half2_rn(f[2 * r], f[2 * r + 1]);

    const uint4* hu = (const uint4*)h;
    g_feat_lo[p] = hu[0];
    g_feat_hi[p] = hu[1];
}

// ---------------------------------------------------------------------------
// Main volume kernel: TWO threads per voxel (8 channels each).
// Lane mapping: plane = tx>>4 (0: ch 0-7 from lo, 1: ch 8-15 from hi), kk = tx&15.
// Halved accumulators (16 regs) -> 5 CTAs/SM -> ~62% occupancy for latency hiding.
// ---------------------------------------------------------------------------
__global__ __launch_bounds__(256, 5) void vol_kernel(float* __restrict__ out,
                                                     const float* __restrict__ intrs,
                                                     const float* __restrict__ c2ws) {
    __shared__ float sM[NV * 12];
    {
        int tid = threadIdx.y * 32 + threadIdx.x;
        if (tid < NV) build_view_matrix(intrs, c2ws, tid, sM + tid * 12);
    }
    __syncthreads();

    const int tx    = threadIdx.x;
    const int plane = tx >> 4;            // 0 -> channels 0-7, 1 -> channels 8-15
    const int kk    = tx & 15;

    const int k = blockIdx.x * 16 + kk;
    const int j = blockIdx.y * 8 + threadIdx.y;
    const int i = blockIdx.z;

    const float step = 2.0f / (DVOL - 1);
    const float wx = -1.0f + i * step;
    const float wy = -1.0f + j * step;
    const float wz = -1.0f + k * step;

    const uint4* planebase = plane ? g_feat_hi : g_feat_lo;

    float sum[8], sq[8];
#pragma unroll
    for (int c = 0; c < 8; c++) { sum[c] = 0.f; sq[c] = 0.f; }
    float cnt = 0.f;

#pragma unroll
    for (int v = 0; v < NV; v++) {
        const float* M = sM + v * 12;
        float px = M[0] * wx + M[1] * wy + M[2]  * wz + M[3];
        float py = M[4] * wx + M[5] * wy + M[6]  * wz + M[7];
        float pz = M[8] * wx + M[9] * wy + M[10] * wz + M[11];
        float zb = pz + 1e-8f;
        // division-free frustum test: for zb>0, |nx|<=1 <=> 0 <= px <= (W-1)*zb
        bool ok = (pz > 0.0f) &&
                  (px >= 0.0f) && (px <= (IMW - 1) * zb) &&
                  (py >= 0.0f) && (py <= (IMH - 1) * zb);
        if (!ok) continue;

        float invz = 1.0f / zb;
        float sx = px * invz, sy = py * invz;
        // mirror reference op order for the sample position
        float nx = sx / ((IMW - 1) * 0.5f) - 1.0f;
        float ny = sy / ((IMH - 1) * 0.5f) - 1.0f;
        float ix = (nx + 1.0f) * 0.5f * (IMW - 1);   // in [0, W-1]
        float iy = (ny + 1.0f) * 0.5f * (IMH - 1);   // in [0, H-1]
        // ix,iy >= 0 here, so trunc == floor; corner 0 always in-bounds.
        int x0 = (int)ix, y0 = (int)iy;
        float wx1 = ix - (float)x0, wy1 = iy - (float)y0;
        float wx0f = 1.0f - wx1, wy0f = 1.0f - wy1;
        bool vx1 = (x0 + 1) < IMW;
        bool vy1 = (y0 + 1) < IMH;
        float w00 = wx0f * wy0f;
        float w10 = vx1 ? wx1 * wy0f : 0.f;
        float w01 = vy1 ? wx0f * wy1 : 0.f;
        float w11 = (vx1 & vy1) ? wx1 * wy1 : 0.f;
        int xs = vx1 ? 1 : 0;
        int o00 = y0 * IMW + x0;
        int o01 = vy1 ? o00 + IMW : o00;
        int o10 = o00 + xs;
        int o11 = o01 + xs;

        __half2 h00 = __float2half2_rn(w00);
        __half2 h10 = __float2half2_rn(w10);
        __half2 h01 = __float2half2_rn(w01);
        __half2 h11 = __float2half2_rn(w11);

        const uint4* fb = planebase + (size_t)v * HW;

        cnt += 1.0f;
        uint4 u00 = __ldg(fb + o00);
        uint4 u10 = __ldg(fb + o10);
        uint4 u01 = __ldg(fb + o01);
        uint4 u11 = __ldg(fb + o11);
        const __half2* p00 = (const __half2*)&u00;
        const __half2* p10 = (const __half2*)&u10;
        const __half2* p01 = (const __half2*)&u01;
        const __half2* p11 = (const __half2*)&u11;
#pragma unroll
        for (int r = 0; r < 4; r++) {
            __half2 acc = __hmul2(p00[r], h00);
            acc = __hfma2(p10[r], h10, acc);
            acc = __hfma2(p01[r], h01, acc);
            acc = __hfma2(p11[r], h11, acc);
            float2 a = __half22float2(acc);
            sum[r * 2]     += a.x;  sq[r * 2]     += a.x * a.x;
            sum[r * 2 + 1] += a.y;  sq[r * 2 + 1] += a.y * a.y;
        }
    }

    const size_t idx = (size_t)i * DVOL * DVOL + (size_t)j * DVOL + k;
    const float rinv = 1.0f / ((cnt <= 0.f) ? 1e-8f : cnt);
    const int chbase = plane * 8;
    // streaming stores: single-touch output must not evict features from L2
#pragma unroll
    for (int c = 0; c < 8; c++) {
        float mean = sum[c] * rinv;
        float var  = sq[c] * rinv - mean * mean;
        __stcs(out + (size_t)(chbase + c) * PVOX + idx, mean);
        __stcs(out + (size_t)(C + chbase + c) * PVOX + idx, var);
    }
    if (plane)
        __stcs(out + (size_t)(2 * C) * PVOX + idx, (cnt > 1.0f) ? 1.0f : 0.0f);  // MIN_VIS_VIEW=1
}

// ---------------------------------------------------------------------------
extern "C" void kernel_launch(void* const* d_in, const int* in_sizes, int n_in,
                              void* d_out, int out_size) {
    const float* feat  = (const float*)d_in[0];  // (6,16,480,640)
    const float* intrs = (const float*)d_in[1];  // (6,3,4)
    const float* c2ws  = (const float*)d_in[2];  // (6,4,4)
    float* out = (float*)d_out;                  // 32*P + P fp32

    int npix = NV * HW;
    transpose_kernel<<<(npix + 255) / 256, 256>>>(feat);

    dim3 blk(32, 8, 1);
    dim3 grd(DVOL / 16, DVOL / 8, DVOL);         // 2 threads per voxel
    vol_kernel<<<grd, blk>>>(out, intrs, c2ws);
}